// round 9
// baseline (speedup 1.0000x reference)
#include <cuda_runtime.h>
#include <cuda_fp16.h>
#include <cstdint>

#define NUM_CODES 100000
#define DIM 64
#define NVISITS 65536
#define LCODES 48

// fp16 pre-scaled tangent table + trailing ZERO row (index NUM_CODES) for
// masked slots. Row = 64 halfs = 128 B = one L2 line. ~12.8 MB, L2-resident.
__device__ __align__(16) __half2 g_tang[(size_t)(NUM_CODES + 1) * (DIM / 2)];

// ---------------------------------------------------------------------------
// Pass 1: tang[c] = (atanh(min(||emb_c||,1-1e-7)) / max(||emb_c||,1e-15)) * emb_c
// One warp per row; lane owns 2 dims. Butterfly norm reduce, Taylor atanh(x)/x
// in the small-norm regime (data: ||x|| ~ 0.008). Warp NUM_CODES zeroes pad row.
// ---------------------------------------------------------------------------
__global__ void __launch_bounds__(256) build_tangents(const float* __restrict__ emb) {
    int warp = (blockIdx.x * blockDim.x + threadIdx.x) >> 5;
    int lane = threadIdx.x & 31;
    if (warp > NUM_CODES) return;

    if (warp == NUM_CODES) {
        g_tang[(size_t)warp * (DIM / 2) + lane] = __half2half2(__ushort_as_half(0));
        return;
    }

    const float2 v = reinterpret_cast<const float2*>(emb + (size_t)warp * DIM)[lane];
    float ss = v.x * v.x + v.y * v.y;
    #pragma unroll
    for (int o = 16; o; o >>= 1)
        ss += __shfl_xor_sync(0xffffffffu, ss, o);

    float s;
    if (ss < 0.09f) {
        // atanh(x)/x = 1 + y/3 + y^2/5 + y^3/7 + y^4/9, y = x^2 = ss.
        s = 1.0f + ss * (0.33333334f + ss * (0.2f + ss * (0.14285715f + ss * 0.11111111f)));
    } else {
        float n = fmaxf(sqrtf(ss), 1e-15f);
        float a = fminf(n, 1.0f - 1e-7f);
        s = atanhf(a) / n;
    }

    g_tang[(size_t)warp * (DIM / 2) + lane] =
        __float22half2_rn(make_float2(s * v.x, s * v.y));
}

// half2 add on raw u32 payloads (HADD2).
__device__ __forceinline__ uint32_t hadd2u(uint32_t a, uint32_t b) {
    uint32_t r;
    asm("add.rn.f16x2 %0, %1, %2;" : "=r"(r) : "r"(a), "r"(b));
    return r;
}

// Convert one half2 to f32x2 and add into a packed f32x2 accumulator.
__device__ __forceinline__ void hacc2(uint32_t h2, unsigned long long& acc) {
    asm("{\n\t"
        ".reg .f16 l, h;\n\t"
        ".reg .f32 fl, fh;\n\t"
        ".reg .b64 fv;\n\t"
        "mov.b32 {l, h}, %1;\n\t"
        "cvt.f32.f16 fl, l;\n\t"
        "cvt.f32.f16 fh, h;\n\t"
        "mov.b64 fv, {fl, fh};\n\t"
        "add.rn.f32x2 %0, %0, fv;\n\t"
        "}" : "+l"(acc) : "r"(h2));
}

// ---------------------------------------------------------------------------
// Pass 2: out[visit] = mean over valid codes of tang[code].
// QUARTER-WARP PER VISIT: each 8-lane quarter owns one visit end-to-end
// (no cross-quarter shuffle tail). One warp-wide LDG.128 fetches 4 table
// rows (one per quarter's visit). Pad ids clamp to the zero row with a
// single IMNMX (no predication, no zero-init MOVs): 3 issues per gather
// instead of 7. 12 groups: broadcast uint4 id load + 4 gathers + two-level
// HADD2 tree + packed f32x2 accumulate. Quarter stores its 256B output row.
// ---------------------------------------------------------------------------
__global__ void __launch_bounds__(256, 6) visit_mean(const int* __restrict__ ids,
                                                     float* __restrict__ out) {
    int warp  = (blockIdx.x * blockDim.x + threadIdx.x) >> 5;
    int lane  = threadIdx.x & 31;
    const int quarter = lane >> 3;
    const int ql      = lane & 7;          // 16B chunk within row: dims [8ql, 8ql+8)

    const int visit = warp * 4 + quarter;  // grid sized so this never overflows

    // 48 ids of this quarter's visit: 12 broadcast uint4 loads.
    const uint4* __restrict__ vid4 =
        reinterpret_cast<const uint4*>(ids + (size_t)visit * LCODES);

    const char* __restrict__ base = reinterpret_cast<const char*>(g_tang) + ql * 16;

    unsigned long long acc[4] = {0ull, 0ull, 0ull, 0ull};
    int cnt = 0;

    #pragma unroll
    for (int g = 0; g < 12; g++) {
        const uint4 idv = __ldg(vid4 + g);
        const int i0 = (int)idv.x, i1 = (int)idv.y, i2 = (int)idv.z, i3 = (int)idv.w;
        cnt += (i0 >= 0) + (i1 >= 0) + (i2 >= 0) + (i3 >= 0);

        // pad (-1) -> 0xFFFFFFFF -> clamps to zero row NUM_CODES (one IMNMX).
        const unsigned c0 = min((unsigned)i0, (unsigned)NUM_CODES);
        const unsigned c1 = min((unsigned)i1, (unsigned)NUM_CODES);
        const unsigned c2 = min((unsigned)i2, (unsigned)NUM_CODES);
        const unsigned c3 = min((unsigned)i3, (unsigned)NUM_CODES);

        const uint4 a = *reinterpret_cast<const uint4*>(base + (size_t)c0 * 128u);
        const uint4 b = *reinterpret_cast<const uint4*>(base + (size_t)c1 * 128u);
        const uint4 c = *reinterpret_cast<const uint4*>(base + (size_t)c2 * 128u);
        const uint4 d = *reinterpret_cast<const uint4*>(base + (size_t)c3 * 128u);

        hacc2(hadd2u(hadd2u(a.x, b.x), hadd2u(c.x, d.x)), acc[0]);
        hacc2(hadd2u(hadd2u(a.y, b.y), hadd2u(c.y, d.y)), acc[1]);
        hacc2(hadd2u(hadd2u(a.z, b.z), hadd2u(c.z, d.z)), acc[2]);
        hacc2(hadd2u(hadd2u(a.w, b.w), hadd2u(c.w, d.w)), acc[3]);
    }

    float f[8];
    #pragma unroll
    for (int j = 0; j < 4; j++) {
        f[2 * j]     = __uint_as_float((unsigned)(acc[j] & 0xffffffffull));
        f[2 * j + 1] = __uint_as_float((unsigned)(acc[j] >> 32));
    }

    const float inv = 1.0f / fmaxf((float)cnt, 1.0f);
    float4 o0 = make_float4(f[0] * inv, f[1] * inv, f[2] * inv, f[3] * inv);
    float4 o1 = make_float4(f[4] * inv, f[5] * inv, f[6] * inv, f[7] * inv);
    float4* op = reinterpret_cast<float4*>(out + (size_t)visit * DIM + ql * 8);
    op[0] = o0;
    op[1] = o1;
}

extern "C" void kernel_launch(void* const* d_in, const int* in_sizes, int n_in,
                              void* d_out, int out_size) {
    const int*   code_ids = (const int*)d_in[0];   // [N, L] int32, -1 = pad
    const float* emb      = (const float*)d_in[1]; // [NUM_CODES, DIM] fp32
    float*       out      = (float*)d_out;         // [N, DIM] fp32

    (void)in_sizes; (void)n_in; (void)out_size;

    build_tangents<<<(NUM_CODES + 1 + 7) / 8, 256>>>(emb);
    // 32 visits per 256-thread block: 65536 / 32 = 2048 blocks.
    visit_mean<<<NVISITS / 32, 256>>>(code_ids, out);
}

// round 10
// speedup vs baseline: 1.0094x; 1.0094x over previous
#include <cuda_runtime.h>
#include <cuda_fp16.h>
#include <cstdint>

#define NUM_CODES 100000
#define DIM 64
#define NVISITS 65536
#define LCODES 48

// fp16 pre-scaled tangent table + trailing ZERO row (index NUM_CODES) for
// masked slots. Row = 64 halfs = 128 B = one L2 line. ~12.8 MB, L2-resident.
__device__ __align__(16) __half2 g_tang[(size_t)(NUM_CODES + 1) * (DIM / 2)];

// ---------------------------------------------------------------------------
// Pass 1: tang[c] = (atanh(min(||emb_c||,1-1e-7)) / max(||emb_c||,1e-15)) * emb_c
// One warp per row; lane owns 2 dims. Butterfly norm reduce, Taylor atanh(x)/x
// in the small-norm regime (data: ||x|| ~ 0.008). Warp NUM_CODES zeroes pad row.
// ---------------------------------------------------------------------------
__global__ void __launch_bounds__(256) build_tangents(const float* __restrict__ emb) {
    int warp = (blockIdx.x * blockDim.x + threadIdx.x) >> 5;
    int lane = threadIdx.x & 31;
    if (warp > NUM_CODES) return;

    if (warp == NUM_CODES) {
        g_tang[(size_t)warp * (DIM / 2) + lane] = __half2half2(__ushort_as_half(0));
        return;
    }

    const float2 v = reinterpret_cast<const float2*>(emb + (size_t)warp * DIM)[lane];
    float ss = v.x * v.x + v.y * v.y;
    #pragma unroll
    for (int o = 16; o; o >>= 1)
        ss += __shfl_xor_sync(0xffffffffu, ss, o);

    float s;
    if (ss < 0.09f) {
        // atanh(x)/x = 1 + y/3 + y^2/5 + y^3/7 + y^4/9, y = x^2 = ss.
        s = 1.0f + ss * (0.33333334f + ss * (0.2f + ss * (0.14285715f + ss * 0.11111111f)));
    } else {
        float n = fmaxf(sqrtf(ss), 1e-15f);
        float a = fminf(n, 1.0f - 1e-7f);
        s = atanhf(a) / n;
    }

    g_tang[(size_t)warp * (DIM / 2) + lane] =
        __float22half2_rn(make_float2(s * v.x, s * v.y));
}

// half2 add on raw u32 payloads (HADD2).
__device__ __forceinline__ uint32_t hadd2u(uint32_t a, uint32_t b) {
    uint32_t r;
    asm("add.rn.f16x2 %0, %1, %2;" : "=r"(r) : "r"(a), "r"(b));
    return r;
}

// Convert one half2 to f32x2 and add into a packed f32x2 accumulator.
__device__ __forceinline__ void hacc2(uint32_t h2, unsigned long long& acc) {
    asm("{\n\t"
        ".reg .f16 l, h;\n\t"
        ".reg .f32 fl, fh;\n\t"
        ".reg .b64 fv;\n\t"
        "mov.b32 {l, h}, %1;\n\t"
        "cvt.f32.f16 fl, l;\n\t"
        "cvt.f32.f16 fh, h;\n\t"
        "mov.b64 fv, {fl, fh};\n\t"
        "add.rn.f32x2 %0, %0, fv;\n\t"
        "}" : "+l"(acc) : "r"(h2));
}

// ---------------------------------------------------------------------------
// Pass 2: out[visit] = mean over valid codes of tang[code].
// QUARTER-WARP PER VISIT (R8 structure): each 8-lane quarter owns one visit
// end-to-end. One warp-wide LDG.128 fetches 4 table rows (one per quarter's
// visit). Pad ids clamp to the zero row with a single IMNMX (replaces R8's
// 4 MOV-zero + ISETP predication per gather: ~190 fewer issues/warp).
// __launch_bounds__(256,5) keeps the ~48-reg budget that lets ptxas batch
// all 4 gathers of a group in flight (the R9 (256,6)/40-reg ceiling killed
// MLP and caused the regression). 12 groups: broadcast uint4 id load +
// 4 gathers + two-level HADD2 tree + packed f32x2 accumulate.
// ---------------------------------------------------------------------------
__global__ void __launch_bounds__(256, 5) visit_mean(const int* __restrict__ ids,
                                                     float* __restrict__ out) {
    int warp  = (blockIdx.x * blockDim.x + threadIdx.x) >> 5;
    int lane  = threadIdx.x & 31;
    const int quarter = lane >> 3;
    const int ql      = lane & 7;          // 16B chunk within row: dims [8ql, 8ql+8)

    const int visit = warp * 4 + quarter;  // grid sized so this never overflows

    // 48 ids of this quarter's visit: 12 broadcast uint4 loads.
    const uint4* __restrict__ vid4 =
        reinterpret_cast<const uint4*>(ids + (size_t)visit * LCODES);

    const char* __restrict__ base = reinterpret_cast<const char*>(g_tang) + ql * 16;

    unsigned long long acc[4] = {0ull, 0ull, 0ull, 0ull};
    int cnt = 0;

    #pragma unroll
    for (int g = 0; g < 12; g++) {
        const uint4 idv = __ldg(vid4 + g);
        const int i0 = (int)idv.x, i1 = (int)idv.y, i2 = (int)idv.z, i3 = (int)idv.w;
        cnt += (i0 >= 0) + (i1 >= 0) + (i2 >= 0) + (i3 >= 0);

        // pad (-1) -> 0xFFFFFFFF -> clamps to zero row NUM_CODES (one IMNMX).
        const unsigned c0 = min((unsigned)i0, (unsigned)NUM_CODES);
        const unsigned c1 = min((unsigned)i1, (unsigned)NUM_CODES);
        const unsigned c2 = min((unsigned)i2, (unsigned)NUM_CODES);
        const unsigned c3 = min((unsigned)i3, (unsigned)NUM_CODES);

        const uint4 a = *reinterpret_cast<const uint4*>(base + (size_t)c0 * 128u);
        const uint4 b = *reinterpret_cast<const uint4*>(base + (size_t)c1 * 128u);
        const uint4 c = *reinterpret_cast<const uint4*>(base + (size_t)c2 * 128u);
        const uint4 d = *reinterpret_cast<const uint4*>(base + (size_t)c3 * 128u);

        hacc2(hadd2u(hadd2u(a.x, b.x), hadd2u(c.x, d.x)), acc[0]);
        hacc2(hadd2u(hadd2u(a.y, b.y), hadd2u(c.y, d.y)), acc[1]);
        hacc2(hadd2u(hadd2u(a.z, b.z), hadd2u(c.z, d.z)), acc[2]);
        hacc2(hadd2u(hadd2u(a.w, b.w), hadd2u(c.w, d.w)), acc[3]);
    }

    float f[8];
    #pragma unroll
    for (int j = 0; j < 4; j++) {
        f[2 * j]     = __uint_as_float((unsigned)(acc[j] & 0xffffffffull));
        f[2 * j + 1] = __uint_as_float((unsigned)(acc[j] >> 32));
    }

    const float inv = 1.0f / fmaxf((float)cnt, 1.0f);
    float4 o0 = make_float4(f[0] * inv, f[1] * inv, f[2] * inv, f[3] * inv);
    float4 o1 = make_float4(f[4] * inv, f[5] * inv, f[6] * inv, f[7] * inv);
    float4* op = reinterpret_cast<float4*>(out + (size_t)visit * DIM + ql * 8);
    op[0] = o0;
    op[1] = o1;
}

extern "C" void kernel_launch(void* const* d_in, const int* in_sizes, int n_in,
                              void* d_out, int out_size) {
    const int*   code_ids = (const int*)d_in[0];   // [N, L] int32, -1 = pad
    const float* emb      = (const float*)d_in[1]; // [NUM_CODES, DIM] fp32
    float*       out      = (float*)d_out;         // [N, DIM] fp32

    (void)in_sizes; (void)n_in; (void)out_size;

    build_tangents<<<(NUM_CODES + 1 + 7) / 8, 256>>>(emb);
    // 32 visits per 256-thread block: 65536 / 32 = 2048 blocks.
    visit_mean<<<NVISITS / 32, 256>>>(code_ids, out);
}

// round 11
// speedup vs baseline: 1.3268x; 1.3145x over previous
#include <cuda_runtime.h>
#include <cuda_fp16.h>
#include <cstdint>

#define NUM_CODES 100000
#define DIM 64
#define NVISITS 65536
#define LCODES 48

// fp16 pre-scaled tangent table. Row = 64 halfs = 128 B = one L2 line.
// ~12.8 MB, L2-resident.
__device__ __align__(16) __half2 g_tang[(size_t)NUM_CODES * (DIM / 2)];

// ---------------------------------------------------------------------------
// Pass 1: tang[c] = (atanh(min(||emb_c||,1-1e-7)) / max(||emb_c||,1e-15)) * emb_c
// One warp per row; lane owns 2 dims. Butterfly norm reduce, Taylor atanh(x)/x
// in the small-norm regime (data: ||x|| ~ 0.008).
// ---------------------------------------------------------------------------
__global__ void __launch_bounds__(256) build_tangents(const float* __restrict__ emb) {
    int warp = (blockIdx.x * blockDim.x + threadIdx.x) >> 5;
    int lane = threadIdx.x & 31;
    if (warp >= NUM_CODES) return;

    const float2 v = reinterpret_cast<const float2*>(emb + (size_t)warp * DIM)[lane];
    float ss = v.x * v.x + v.y * v.y;
    #pragma unroll
    for (int o = 16; o; o >>= 1)
        ss += __shfl_xor_sync(0xffffffffu, ss, o);

    float s;
    if (ss < 0.09f) {
        // atanh(x)/x = 1 + y/3 + y^2/5 + y^3/7 + y^4/9, y = x^2 = ss.
        s = 1.0f + ss * (0.33333334f + ss * (0.2f + ss * (0.14285715f + ss * 0.11111111f)));
    } else {
        float n = fmaxf(sqrtf(ss), 1e-15f);
        float a = fminf(n, 1.0f - 1e-7f);
        s = atanhf(a) / n;
    }

    g_tang[(size_t)warp * (DIM / 2) + lane] =
        __float22half2_rn(make_float2(s * v.x, s * v.y));
}

// half2 add on raw u32 payloads (HADD2).
__device__ __forceinline__ uint32_t hadd2u(uint32_t a, uint32_t b) {
    uint32_t r;
    asm("add.rn.f16x2 %0, %1, %2;" : "=r"(r) : "r"(a), "r"(b));
    return r;
}

// Convert one half2 to f32x2 and add into a packed f32x2 accumulator.
__device__ __forceinline__ void hacc2(uint32_t h2, unsigned long long& acc) {
    asm("{\n\t"
        ".reg .f16 l, h;\n\t"
        ".reg .f32 fl, fh;\n\t"
        ".reg .b64 fv;\n\t"
        "mov.b32 {l, h}, %1;\n\t"
        "cvt.f32.f16 fl, l;\n\t"
        "cvt.f32.f16 fh, h;\n\t"
        "mov.b64 fv, {fl, fh};\n\t"
        "add.rn.f32x2 %0, %0, fv;\n\t"
        "}" : "+l"(acc) : "r"(h2));
}

// Predicated 16B gather: returns zeros when pred is false, no memory traffic.
__device__ __forceinline__ uint4 gather_pred(bool pred, const char* p) {
    uint4 r = make_uint4(0u, 0u, 0u, 0u);
    if (pred) r = *reinterpret_cast<const uint4*>(p);
    return r;
}

// ---------------------------------------------------------------------------
// Pass 2: out[visit] = mean over valid codes of tang[code].
// QUARTER-WARP PER VISIT (R8 structure, best measured): each 8-lane quarter
// owns one visit end-to-end; one warp-wide LDG.128 fetches 4 table rows.
// Pad slots use PREDICATED loads (zero-filled, no wavefronts) -- the A/B
// tests of R8 vs R9/R10 showed predication beats the zero-row clamp.
// NEW: 8-wide fp16 pairwise tree -- two id-groups (8 codes) share one
// HADD2 tree, halving the fp16->fp32 conversion count (6 instead of 12
// hacc2 per component stream).
// ---------------------------------------------------------------------------
__global__ void __launch_bounds__(256, 5) visit_mean(const int* __restrict__ ids,
                                                     float* __restrict__ out) {
    int warp  = (blockIdx.x * blockDim.x + threadIdx.x) >> 5;
    int lane  = threadIdx.x & 31;
    const int quarter = lane >> 3;
    const int ql      = lane & 7;          // 16B chunk within row: dims [8ql, 8ql+8)

    const int visit = warp * 4 + quarter;  // grid sized so this never overflows

    // 48 ids of this quarter's visit: 12 broadcast uint4 loads.
    const uint4* __restrict__ vid4 =
        reinterpret_cast<const uint4*>(ids + (size_t)visit * LCODES);

    const char* __restrict__ base = reinterpret_cast<const char*>(g_tang) + ql * 16;

    unsigned long long acc[4] = {0ull, 0ull, 0ull, 0ull};
    int cnt = 0;

    #pragma unroll
    for (int gg = 0; gg < 6; gg++) {       // 6 supergroups of 8 codes
        const uint4 idv0 = __ldg(vid4 + 2 * gg);
        const uint4 idv1 = __ldg(vid4 + 2 * gg + 1);

        const int i0 = (int)idv0.x, i1 = (int)idv0.y, i2 = (int)idv0.z, i3 = (int)idv0.w;
        const int i4 = (int)idv1.x, i5 = (int)idv1.y, i6 = (int)idv1.z, i7 = (int)idv1.w;
        cnt += (i0 >= 0) + (i1 >= 0) + (i2 >= 0) + (i3 >= 0)
             + (i4 >= 0) + (i5 >= 0) + (i6 >= 0) + (i7 >= 0);

        const uint4 a = gather_pred(i0 >= 0, base + (size_t)(unsigned)i0 * 128u);
        const uint4 b = gather_pred(i1 >= 0, base + (size_t)(unsigned)i1 * 128u);
        const uint4 c = gather_pred(i2 >= 0, base + (size_t)(unsigned)i2 * 128u);
        const uint4 d = gather_pred(i3 >= 0, base + (size_t)(unsigned)i3 * 128u);
        const uint4 e = gather_pred(i4 >= 0, base + (size_t)(unsigned)i4 * 128u);
        const uint4 h = gather_pred(i5 >= 0, base + (size_t)(unsigned)i5 * 128u);
        const uint4 p = gather_pred(i6 >= 0, base + (size_t)(unsigned)i6 * 128u);
        const uint4 q = gather_pred(i7 >= 0, base + (size_t)(unsigned)i7 * 128u);

        // 8-wide balanced fp16 tree per component, single fp32 accumulate.
        hacc2(hadd2u(hadd2u(hadd2u(a.x, b.x), hadd2u(c.x, d.x)),
                     hadd2u(hadd2u(e.x, h.x), hadd2u(p.x, q.x))), acc[0]);
        hacc2(hadd2u(hadd2u(hadd2u(a.y, b.y), hadd2u(c.y, d.y)),
                     hadd2u(hadd2u(e.y, h.y), hadd2u(p.y, q.y))), acc[1]);
        hacc2(hadd2u(hadd2u(hadd2u(a.z, b.z), hadd2u(c.z, d.z)),
                     hadd2u(hadd2u(e.z, h.z), hadd2u(p.z, q.z))), acc[2]);
        hacc2(hadd2u(hadd2u(hadd2u(a.w, b.w), hadd2u(c.w, d.w)),
                     hadd2u(hadd2u(e.w, h.w), hadd2u(p.w, q.w))), acc[3]);
    }

    float f[8];
    #pragma unroll
    for (int j = 0; j < 4; j++) {
        f[2 * j]     = __uint_as_float((unsigned)(acc[j] & 0xffffffffull));
        f[2 * j + 1] = __uint_as_float((unsigned)(acc[j] >> 32));
    }

    const float inv = 1.0f / fmaxf((float)cnt, 1.0f);
    float4 o0 = make_float4(f[0] * inv, f[1] * inv, f[2] * inv, f[3] * inv);
    float4 o1 = make_float4(f[4] * inv, f[5] * inv, f[6] * inv, f[7] * inv);
    float4* op = reinterpret_cast<float4*>(out + (size_t)visit * DIM + ql * 8);
    op[0] = o0;
    op[1] = o1;
}

extern "C" void kernel_launch(void* const* d_in, const int* in_sizes, int n_in,
                              void* d_out, int out_size) {
    const int*   code_ids = (const int*)d_in[0];   // [N, L] int32, -1 = pad
    const float* emb      = (const float*)d_in[1]; // [NUM_CODES, DIM] fp32
    float*       out      = (float*)d_out;         // [N, DIM] fp32

    (void)in_sizes; (void)n_in; (void)out_size;

    build_tangents<<<(NUM_CODES + 7) / 8, 256>>>(emb);
    // 32 visits per 256-thread block: 65536 / 32 = 2048 blocks.
    visit_mean<<<NVISITS / 32, 256>>>(code_ids, out);
}